// round 3
// baseline (speedup 1.0000x reference)
#include <cuda_runtime.h>
#include <cuda_bf16.h>
#include <math.h>

#define SEQ 4096
#define NF 2048
#define HID 1024
#define GATES 4096
#define TAGS 10
#define START_TAG 8
#define STOP_TAG 9
#define NCTA 74        // CTAs per direction in the scan
#define NHC 14         // h-elements owned per CTA (74*14 >= 1024)
#define ROWS 56        // 4 gates * NHC weight rows per CTA

// ---------------- scratch (module-static; no runtime allocation) ----------------
__device__ float g_xp[2][SEQ][GATES];   // precomputed input projections (134 MB)
__device__ float g_h[2][SEQ][HID];      // per-direction hidden states (33.5 MB)
__device__ float g_feats[SEQ][TAGS];
__device__ unsigned g_cnt[2];           // per-direction step-arrival counters

__global__ void init_kernel() {
    if (threadIdx.x < 2) g_cnt[threadIdx.x] = 0u;
}

// ---------------- Kernel 1: xp = X @ W_ih^T + b  (both directions) ----------------
// C[t][g] = sum_k X[t][k] * W[g][k] ; register-tiled SGEMM 128x128x8, 256 thr, 8x8/thr
__global__ void __launch_bounds__(256) gemm_xp(const float* __restrict__ X,
                                               const float* __restrict__ Wf,
                                               const float* __restrict__ bf,
                                               const float* __restrict__ Wb,
                                               const float* __restrict__ bb)
{
    const int dir = blockIdx.z;
    const float* __restrict__ Wg   = dir ? Wb : Wf;
    const float* __restrict__ bias = dir ? bb : bf;

    __shared__ float As[8][128];
    __shared__ float Bs[8][128];

    const int tid = threadIdx.x;
    const int tx = tid & 15, ty = tid >> 4;
    const int bm = blockIdx.y * 128;   // t block
    const int bn = blockIdx.x * 128;   // gate block

    float acc[8][8];
#pragma unroll
    for (int i = 0; i < 8; i++)
#pragma unroll
        for (int j = 0; j < 8; j++) acc[i][j] = 0.f;

    const int lr = tid >> 1;           // 0..127
    const int lc = (tid & 1) * 4;      // 0 or 4
    const float* Ap = X  + (size_t)(bm + lr) * NF + lc;
    const float* Bp = Wg + (size_t)(bn + lr) * NF + lc;

    for (int k0 = 0; k0 < NF; k0 += 8) {
        float4 a = *(const float4*)(Ap + k0);
        float4 b = *(const float4*)(Bp + k0);
        As[lc + 0][lr] = a.x; As[lc + 1][lr] = a.y; As[lc + 2][lr] = a.z; As[lc + 3][lr] = a.w;
        Bs[lc + 0][lr] = b.x; Bs[lc + 1][lr] = b.y; Bs[lc + 2][lr] = b.z; Bs[lc + 3][lr] = b.w;
        __syncthreads();
#pragma unroll
        for (int k = 0; k < 8; k++) {
            float ra[8], rb[8];
#pragma unroll
            for (int i = 0; i < 8; i++) ra[i] = As[k][ty * 8 + i];
#pragma unroll
            for (int j = 0; j < 8; j++) rb[j] = Bs[k][tx * 8 + j];
#pragma unroll
            for (int i = 0; i < 8; i++)
#pragma unroll
                for (int j = 0; j < 8; j++) acc[i][j] = fmaf(ra[i], rb[j], acc[i][j]);
        }
        __syncthreads();
    }

#pragma unroll
    for (int i = 0; i < 8; i++) {
        const int t = bm + ty * 8 + i;
#pragma unroll
        for (int j = 0; j < 8; j++) {
            const int g = bn + tx * 8 + j;
            g_xp[dir][t][g] = acc[i][j] + bias[g];
        }
    }
}

// ---------------- Kernel 2: persistent bidirectional LSTM scan ----------------
__device__ __forceinline__ float sigf(float x) { return 1.0f / (1.0f + expf(-x)); }

__global__ void __launch_bounds__(256) lstm_scan(const float* __restrict__ Whf,
                                                 const float* __restrict__ Whb)
{
    extern __shared__ float Wsh[];                // [ROWS][HID] fp32 weight slice
    __shared__ float rowsum[64];
    __shared__ float xps[64];

    const int dir = (blockIdx.x >= NCTA) ? 1 : 0;
    const int ci  = blockIdx.x - dir * NCTA;
    const float* __restrict__ W = dir ? Whb : Whf;
    const int hstart = ci * NHC;

    const int tid  = threadIdx.x;
    const int lane = tid & 31;
    const int warp = tid >> 5;

    // Load this CTA's W_hh slice into SMEM: row r = gate*NHC + localh
    // One 1024-float row per iteration, 256 float4 loads = whole block, coalesced.
    for (int r = 0; r < ROWS; ++r) {
        const int gate = r / NHC, lh = r % NHC;
        const int hg = hstart + lh;
        float4 v = make_float4(0.f, 0.f, 0.f, 0.f);
        if (hg < HID) v = *(const float4*)&W[(size_t)(gate * HID + hg) * HID + tid * 4];
        *(float4*)&Wsh[r * HID + tid * 4] = v;
    }
    // First timestep's xp values
    {
        const int time0 = dir ? (SEQ - 1) : 0;
        if (tid < ROWS) {
            const int gate = tid / NHC;
            const int hg = hstart + tid % NHC;
            xps[tid] = (hg < HID) ? g_xp[dir][time0][gate * HID + hg] : 0.f;
        }
    }
    float creg = 0.f;   // cell state owned by threads tid < NHC
    __syncthreads();

    for (int t = 0; t < SEQ; ++t) {
        const int time = dir ? (SEQ - 1 - t) : t;

        if (t > 0) {
            if (tid == 0) {
                const unsigned target = (unsigned)(NCTA * t);
                while (*((volatile unsigned*)&g_cnt[dir]) < target) { }
            }
            __syncthreads();
            __threadfence();   // acquire: order h loads after counter observation
        }

        // Load h_{prev} (fresh address each step -> no stale L1)
        float4 hreg[8];
        if (t > 0) {
            const int pt = dir ? (time + 1) : (time - 1);
            const float4* hp = (const float4*)&g_h[dir][pt][0];
#pragma unroll
            for (int j = 0; j < 8; j++) hreg[j] = hp[j * 32 + lane];
        } else {
#pragma unroll
            for (int j = 0; j < 8; j++) hreg[j] = make_float4(0.f, 0.f, 0.f, 0.f);
        }

        // 7 gate rows per warp: dot(W_row, h) via SMEM stream + shuffle reduce
#pragma unroll
        for (int rr = 0; rr < 7; ++rr) {
            const int r = warp * 7 + rr;
            float s = 0.f;
            const float4* wr = (const float4*)&Wsh[r * HID];
#pragma unroll
            for (int j = 0; j < 8; j++) {
                const float4 w = wr[j * 32 + lane];
                s = fmaf(w.x, hreg[j].x, s);
                s = fmaf(w.y, hreg[j].y, s);
                s = fmaf(w.z, hreg[j].z, s);
                s = fmaf(w.w, hreg[j].w, s);
            }
#pragma unroll
            for (int off = 16; off; off >>= 1) s += __shfl_xor_sync(0xffffffffu, s, off);
            if (lane == 0) rowsum[r] = s + xps[r];
        }

        // Prefetch next step's xp (independent of h, hides L2 latency)
        float pf = 0.f;
        if (tid < ROWS && t + 1 < SEQ) {
            const int nt = dir ? (time - 1) : (time + 1);
            const int gate = tid / NHC;
            const int hg = hstart + tid % NHC;
            if (hg < HID) pf = g_xp[dir][nt][gate * HID + hg];
        }
        __syncthreads();

        // Gate nonlinearity + state update for owned h elements
        if (tid < NHC) {
            const int hg = hstart + tid;
            const float gi = rowsum[tid];
            const float gf = rowsum[NHC + tid];
            const float gg = rowsum[2 * NHC + tid];
            const float go = rowsum[3 * NHC + tid];
            const float c = sigf(gf) * creg + sigf(gi) * tanhf(gg);
            const float h = sigf(go) * tanhf(c);
            creg = c;
            if (hg < HID) g_h[dir][time][hg] = h;
        }
        if (tid < ROWS) xps[tid] = pf;

        __threadfence();     // release: make h writes GPU-visible before arrive
        __syncthreads();
        if (tid == 0) atomicAdd(&g_cnt[dir], 1u);
    }
}

// ---------------- Kernel 3: feats[t] = W_lin @ concat(h_f[t], h_b[t]) + b_lin ----------------
__global__ void __launch_bounds__(320) feats_kernel(const float* __restrict__ Wl,
                                                    const float* __restrict__ bl)
{
    const int t = blockIdx.x;
    const int warp = threadIdx.x >> 5;   // = tag, exactly 10 warps
    const int lane = threadIdx.x & 31;
    const float* hf = &g_h[0][t][0];
    const float* hb = &g_h[1][t][0];
    const float* w  = &Wl[warp * (2 * HID)];
    float s = 0.f;
    for (int k = lane; k < HID; k += 32) s = fmaf(hf[k], w[k], s);
    for (int k = lane; k < HID; k += 32) s = fmaf(hb[k], w[HID + k], s);
#pragma unroll
    for (int off = 16; off; off >>= 1) s += __shfl_xor_sync(0xffffffffu, s, off);
    if (lane == 0) g_feats[t][warp] = s + bl[warp];
}

// ---------------- Kernel 4: Viterbi (sequential, warp-shuffle recurrence) ----------------
__global__ void __launch_bounds__(256) viterbi_kernel(const float* __restrict__ trans,
                                                      float* __restrict__ out, int out_size)
{
    extern __shared__ float sh[];
    float* sfeats = sh;                                     // SEQ*TAGS floats
    unsigned char* bps = (unsigned char*)(sh + SEQ * TAGS); // SEQ*TAGS bytes

    const int tid = threadIdx.x;
    const float* gf = &g_feats[0][0];
    for (int i = tid; i < SEQ * TAGS; i += blockDim.x) sfeats[i] = gf[i];
    __syncthreads();

    if (tid < 32) {
        const int j = tid;      // lane j holds fv[j]
        float tt[TAGS];
#pragma unroll
        for (int i = 0; i < TAGS; i++) tt[i] = (j < TAGS) ? trans[j * TAGS + i] : 0.f;

        float fv = (j == START_TAG) ? 0.f : -10000.f;
        for (int t = 0; t < SEQ; ++t) {
            float best = -3.4e38f; int arg = 0;
#pragma unroll
            for (int i = 0; i < TAGS; i++) {
                const float v = __shfl_sync(0xffffffffu, fv, i);
                const float sc = v + tt[i];
                if (sc > best) { best = sc; arg = i; }   // strict > keeps first argmax
            }
            const float feat = (j < TAGS) ? sfeats[t * TAGS + j] : 0.f;
            fv = best + feat;
            if (j < TAGS) bps[t * TAGS + j] = (unsigned char)arg;
        }

        float term = (j < TAGS) ? (fv + trans[STOP_TAG * TAGS + j]) : -3.4e38f;
        float bscore = -3.4e38f; int btag = 0;
#pragma unroll
        for (int i = 0; i < TAGS; i++) {
            const float v = __shfl_sync(0xffffffffu, term, i);
            if (v > bscore) { bscore = v; btag = i; }
        }

        if (j == 0) {
            out[0] = bscore;
            int tag = btag;
            for (int t = SEQ - 1; t >= 0; --t) {
                if (1 + t < out_size) out[1 + t] = (float)tag;
                tag = bps[t * TAGS + tag];
            }
        }
    }
}

// ---------------- launch ----------------
extern "C" void kernel_launch(void* const* d_in, const int* in_sizes, int n_in,
                              void* d_out, int out_size)
{
    const float* sentence = (const float*)d_in[0];
    const float* W_ih_f   = (const float*)d_in[1];
    const float* W_hh_f   = (const float*)d_in[2];
    const float* b_f      = (const float*)d_in[3];
    const float* W_ih_b   = (const float*)d_in[4];
    const float* W_hh_b   = (const float*)d_in[5];
    const float* b_b      = (const float*)d_in[6];
    const float* W_lin    = (const float*)d_in[7];
    const float* b_lin    = (const float*)d_in[8];
    const float* trans    = (const float*)d_in[9];

    cudaFuncSetAttribute(lstm_scan, cudaFuncAttributeMaxDynamicSharedMemorySize,
                         ROWS * HID * (int)sizeof(float));                 // 229376 B
    cudaFuncSetAttribute(viterbi_kernel, cudaFuncAttributeMaxDynamicSharedMemorySize,
                         SEQ * TAGS * 5);                                   // 204800 B

    init_kernel<<<1, 32>>>();

    dim3 gg(GATES / 128, SEQ / 128, 2);
    gemm_xp<<<gg, 256>>>(sentence, W_ih_f, b_f, W_ih_b, b_b);

    lstm_scan<<<2 * NCTA, 256, ROWS * HID * (int)sizeof(float)>>>(W_hh_f, W_hh_b);

    feats_kernel<<<SEQ, 320>>>(W_lin, b_lin);

    viterbi_kernel<<<1, 256, SEQ * TAGS * 5>>>(trans, (float*)d_out, out_size);
}

// round 5
// speedup vs baseline: 1.4267x; 1.4267x over previous
#include <cuda_runtime.h>
#include <cuda_bf16.h>
#include <math.h>

#define SEQ 4096
#define NF 2048
#define HID 1024
#define GATES 4096
#define TAGS 10
#define START_TAG 8
#define STOP_TAG 9
#define NCTA 74        // CTAs per direction in the scan
#define NHC 14         // h-elements owned per CTA (74*14 >= 1024)
#define ROWS 56        // 4 gates * NHC weight rows per CTA
#define NJR 6          // weight col-chunks held in registers (j=0..5); j=6,7 in SMEM

// packed f32x2 FMA: d = a*b + d (per 32-bit half, exact fp32)
#define FFMA2(d, a, b) asm("fma.rn.f32x2 %0, %1, %2, %3;" \
                           : "=l"(d) : "l"(a), "l"(b), "l"(d))
#define PACKF2(out, lo, hi) asm("mov.b64 %0, {%1, %2};" : "=l"(out) : "f"(lo), "f"(hi))
#define UNPACKF2(lo, hi, in) asm("mov.b64 {%0, %1}, %2;" : "=f"(lo), "=f"(hi) : "l"(in))

// ---------------- scratch (module-static; no runtime allocation) ----------------
__device__ float g_xp[2][SEQ][GATES];   // precomputed input projections
__device__ float g_h[2][SEQ][HID];      // per-direction hidden states
__device__ float g_feats[SEQ][TAGS];
__device__ unsigned g_cnt[2];           // per-direction step-arrival counters

__global__ void init_kernel() {
    if (threadIdx.x < 2) g_cnt[threadIdx.x] = 0u;
}

// ---------------- Kernel 1: xp = X @ W_ih^T + b  (both directions) ----------------
// 128x128x8 tile, 256 thr, 8x8/thr via f32x2 packed FMA, conflict-free vector LDS.
__global__ void __launch_bounds__(256, 2) gemm_xp(const float* __restrict__ X,
                                                  const float* __restrict__ Wf,
                                                  const float* __restrict__ bf,
                                                  const float* __restrict__ Wb,
                                                  const float* __restrict__ bb)
{
    const int dir = blockIdx.z;
    const float* __restrict__ Wg   = dir ? Wb : Wf;
    const float* __restrict__ bias = dir ? bb : bf;

    __shared__ __align__(16) float As[8][128];
    __shared__ __align__(16) float Bs[8][128];

    const int tid = threadIdx.x;
    const int tx = tid & 15, ty = tid >> 4;
    const int bm = blockIdx.y * 128;   // t block
    const int bn = blockIdx.x * 128;   // gate block

    // acc2[i][jp]: row i (8 rows), col-pair jp (4 pairs = 8 cols)
    unsigned long long acc2[8][4];
#pragma unroll
    for (int i = 0; i < 8; i++)
#pragma unroll
        for (int j = 0; j < 4; j++) acc2[i][j] = 0ull;

    const int lr = tid >> 1;           // 0..127
    const int lc = (tid & 1) * 4;      // 0 or 4
    const float* Ap = X  + (size_t)(bm + lr) * NF + lc;
    const float* Bp = Wg + (size_t)(bn + lr) * NF + lc;

    for (int k0 = 0; k0 < NF; k0 += 8) {
        float4 a = *(const float4*)(Ap + k0);
        float4 b = *(const float4*)(Bp + k0);
        __syncthreads();
        As[lc + 0][lr] = a.x; As[lc + 1][lr] = a.y; As[lc + 2][lr] = a.z; As[lc + 3][lr] = a.w;
        Bs[lc + 0][lr] = b.x; Bs[lc + 1][lr] = b.y; Bs[lc + 2][lr] = b.z; Bs[lc + 3][lr] = b.w;
        __syncthreads();
#pragma unroll
        for (int k = 0; k < 8; k++) {
            // rows: ty*4..+3 and 64+ty*4..+3 ; cols: tx*4..+3 and 64+tx*4..+3
            float4 a0 = *(const float4*)&As[k][ty * 4];
            float4 a1 = *(const float4*)&As[k][64 + ty * 4];
            ulonglong2 b0 = *(const ulonglong2*)&Bs[k][tx * 4];
            ulonglong2 b1 = *(const ulonglong2*)&Bs[k][64 + tx * 4];
            float av[8] = {a0.x, a0.y, a0.z, a0.w, a1.x, a1.y, a1.z, a1.w};
#pragma unroll
            for (int i = 0; i < 8; i++) {
                unsigned long long ad;
                PACKF2(ad, av[i], av[i]);
                FFMA2(acc2[i][0], ad, b0.x);
                FFMA2(acc2[i][1], ad, b0.y);
                FFMA2(acc2[i][2], ad, b1.x);
                FFMA2(acc2[i][3], ad, b1.y);
            }
        }
    }

#pragma unroll
    for (int i = 0; i < 8; i++) {
        const int row = bm + ((i < 4) ? (ty * 4 + i) : (64 + ty * 4 + i - 4));
#pragma unroll
        for (int jp = 0; jp < 4; jp++) {
            const int col = bn + ((jp < 2) ? (tx * 4 + jp * 2) : (64 + tx * 4 + (jp - 2) * 2));
            float lo, hi;
            UNPACKF2(lo, hi, acc2[i][jp]);
            g_xp[dir][row][col + 0] = lo + bias[col + 0];
            g_xp[dir][row][col + 1] = hi + bias[col + 1];
        }
    }
}

// ---------------- Kernel 2: persistent bidirectional LSTM scan ----------------
// W_hh slice: cols 0..767 in REGISTERS (168 regs/thread), cols 768..1023 in SMEM.
__device__ __forceinline__ float sigf(float x) { return 1.0f / (1.0f + expf(-x)); }

__global__ void __launch_bounds__(256, 1) lstm_scan(const float* __restrict__ Whf,
                                                    const float* __restrict__ Whb)
{
    extern __shared__ __align__(16) float Wsh[];  // [ROWS][256] cols 768..1023
    __shared__ float rowsum[64];
    __shared__ float xps[64];

    const int dir = (blockIdx.x >= NCTA) ? 1 : 0;
    const int ci  = blockIdx.x - dir * NCTA;
    const float* __restrict__ W = dir ? Whb : Whf;
    const int hstart = ci * NHC;

    const int tid  = threadIdx.x;
    const int lane = tid & 31;
    const int warp = tid >> 5;
    const int rbase = warp * 7;

    // ---- load register-resident weight chunks (cols 0..767) ----
    unsigned long long wreg[7][NJR][2];
#pragma unroll
    for (int rr = 0; rr < 7; rr++) {
        const int r = rbase + rr;
        const int gate = r / NHC, lh = r % NHC;
        int hg = hstart + lh; if (hg >= HID) hg = HID - 1;  // clamp; values unused
        const float* wrow = W + (size_t)(gate * HID + hg) * HID;
#pragma unroll
        for (int j = 0; j < NJR; j++) {
            float4 v = *(const float4*)&wrow[j * 128 + lane * 4];
            PACKF2(wreg[rr][j][0], v.x, v.y);
            PACKF2(wreg[rr][j][1], v.z, v.w);
        }
    }
    // ---- cooperative SMEM load of cols 768..1023 ----
    for (int idx = tid; idx < ROWS * 64; idx += 256) {
        const int r = idx >> 6, c4 = idx & 63;
        const int gate = r / NHC, lh = r % NHC;
        int hg = hstart + lh; if (hg >= HID) hg = HID - 1;
        float4 v = *(const float4*)&W[(size_t)(gate * HID + hg) * HID + 768 + c4 * 4];
        *(float4*)&Wsh[r * 256 + c4 * 4] = v;
    }
    // first timestep's xp
    {
        const int time0 = dir ? (SEQ - 1) : 0;
        if (tid < ROWS) {
            const int gate = tid / NHC;
            int hg = hstart + tid % NHC; if (hg >= HID) hg = HID - 1;
            xps[tid] = g_xp[dir][time0][gate * HID + hg];
        }
    }
    float creg = 0.f;
    __syncthreads();

    for (int t = 0; t < SEQ; ++t) {
        const int time = dir ? (SEQ - 1 - t) : t;

        if (t > 0) {
            if (tid == 0) {
                const unsigned target = (unsigned)(NCTA * t);
                unsigned v;
                do {
                    asm volatile("ld.acquire.gpu.global.u32 %0, [%1];"
                                 : "=r"(v) : "l"(&g_cnt[dir]) : "memory");
                } while (v < target);
            }
            __syncthreads();
        }

        // load h_{prev} as packed f32x2 pairs; issue all 8 vectors (MLP=8)
        ulonglong2 hv2[8];
        if (t > 0) {
            const int pt = dir ? (time + 1) : (time - 1);
            const ulonglong2* hp = (const ulonglong2*)&g_h[dir][pt][0];
#pragma unroll
            for (int j = 0; j < 8; j++) hv2[j] = hp[j * 32 + lane];
        } else {
#pragma unroll
            for (int j = 0; j < 8; j++) { hv2[j].x = 0ull; hv2[j].y = 0ull; }
        }

        // prefetch next step's xp (independent of h)
        float pf = 0.f;
        if (tid < ROWS && t + 1 < SEQ) {
            const int nt = dir ? (time - 1) : (time + 1);
            const int gate = tid / NHC;
            int hg = hstart + tid % NHC; if (hg >= HID) hg = HID - 1;
            pf = g_xp[dir][nt][gate * HID + hg];
        }

        // dot products: register chunks then SMEM chunks, f32x2 accumulation
        unsigned long long acc2[7];
#pragma unroll
        for (int rr = 0; rr < 7; rr++) acc2[rr] = 0ull;
#pragma unroll
        for (int j = 0; j < NJR; j++) {
#pragma unroll
            for (int rr = 0; rr < 7; rr++) {
                FFMA2(acc2[rr], wreg[rr][j][0], hv2[j].x);
                FFMA2(acc2[rr], wreg[rr][j][1], hv2[j].y);
            }
        }
#pragma unroll
        for (int j = NJR; j < 8; j++) {
#pragma unroll
            for (int rr = 0; rr < 7; rr++) {
                ulonglong2 w2 = *(const ulonglong2*)&Wsh[(rbase + rr) * 256 + (j - NJR) * 128 + lane * 4];
                FFMA2(acc2[rr], w2.x, hv2[j].x);
                FFMA2(acc2[rr], w2.y, hv2[j].y);
            }
        }
#pragma unroll
        for (int rr = 0; rr < 7; rr++) {
            float lo, hi;
            UNPACKF2(lo, hi, acc2[rr]);
            float s = lo + hi;
#pragma unroll
            for (int off = 16; off; off >>= 1) s += __shfl_xor_sync(0xffffffffu, s, off);
            if (lane == 0) rowsum[rbase + rr] = s + xps[rbase + rr];
        }
        __syncthreads();

        // gate nonlinearity + state update
        if (tid < NHC) {
            const int hg = hstart + tid;
            const float gi = rowsum[tid];
            const float gf = rowsum[NHC + tid];
            const float gg = rowsum[2 * NHC + tid];
            const float go = rowsum[3 * NHC + tid];
            const float c = sigf(gf) * creg + sigf(gi) * tanhf(gg);
            const float h = sigf(go) * tanhf(c);
            creg = c;
            if (hg < HID) g_h[dir][time][hg] = h;
        }
        if (tid < ROWS) xps[tid] = pf;

        __syncthreads();                       // all h stores done CTA-wide
        if (tid == 0) {                        // release-arrive (CG grid-barrier idiom)
            unsigned one = 1u;
            asm volatile("red.release.gpu.global.add.u32 [%0], %1;"
                         :: "l"(&g_cnt[dir]), "r"(one) : "memory");
        }
    }
}

// ---------------- Kernel 3: feats[t] = W_lin @ concat(h_f[t], h_b[t]) + b_lin ----------------
__global__ void __launch_bounds__(320) feats_kernel(const float* __restrict__ Wl,
                                                    const float* __restrict__ bl)
{
    const int t = blockIdx.x;
    const int warp = threadIdx.x >> 5;   // = tag, exactly 10 warps
    const int lane = threadIdx.x & 31;
    const float* hf = &g_h[0][t][0];
    const float* hb = &g_h[1][t][0];
    const float* w  = &Wl[warp * (2 * HID)];
    float s = 0.f;
    for (int k = lane; k < HID; k += 32) s = fmaf(hf[k], w[k], s);
    for (int k = lane; k < HID; k += 32) s = fmaf(hb[k], w[HID + k], s);
#pragma unroll
    for (int off = 16; off; off >>= 1) s += __shfl_xor_sync(0xffffffffu, s, off);
    if (lane == 0) g_feats[t][warp] = s + bl[warp];
}

// ---------------- Kernel 4: Viterbi (sequential, warp-shuffle recurrence) ----------------
__global__ void __launch_bounds__(256) viterbi_kernel(const float* __restrict__ trans,
                                                      float* __restrict__ out, int out_size)
{
    extern __shared__ float sh[];
    float* sfeats = sh;                                     // SEQ*TAGS floats
    unsigned char* bps = (unsigned char*)(sh + SEQ * TAGS); // SEQ*TAGS bytes

    const int tid = threadIdx.x;
    const float* gf = &g_feats[0][0];
    for (int i = tid; i < SEQ * TAGS; i += blockDim.x) sfeats[i] = gf[i];
    __syncthreads();

    if (tid < 32) {
        const int j = tid;      // lane j holds fv[j]
        float tt[TAGS];
#pragma unroll
        for (int i = 0; i < TAGS; i++) tt[i] = (j < TAGS) ? trans[j * TAGS + i] : 0.f;

        float fv = (j == START_TAG) ? 0.f : -10000.f;
        for (int t = 0; t < SEQ; ++t) {
            float best = -3.4e38f; int arg = 0;
#pragma unroll
            for (int i = 0; i < TAGS; i++) {
                const float v = __shfl_sync(0xffffffffu, fv, i);
                const float sc = v + tt[i];
                if (sc > best) { best = sc; arg = i; }   // strict > keeps first argmax
            }
            const float feat = (j < TAGS) ? sfeats[t * TAGS + j] : 0.f;
            fv = best + feat;
            if (j < TAGS) bps[t * TAGS + j] = (unsigned char)arg;
        }

        float term = (j < TAGS) ? (fv + trans[STOP_TAG * TAGS + j]) : -3.4e38f;
        float bscore = -3.4e38f; int btag = 0;
#pragma unroll
        for (int i = 0; i < TAGS; i++) {
            const float v = __shfl_sync(0xffffffffu, term, i);
            if (v > bscore) { bscore = v; btag = i; }
        }

        if (j == 0) {
            out[0] = bscore;
            int tag = btag;
            for (int t = SEQ - 1; t >= 0; --t) {
                if (1 + t < out_size) out[1 + t] = (float)tag;
                tag = bps[t * TAGS + tag];
            }
        }
    }
}

// ---------------- launch ----------------
extern "C" void kernel_launch(void* const* d_in, const int* in_sizes, int n_in,
                              void* d_out, int out_size)
{
    const float* sentence = (const float*)d_in[0];
    const float* W_ih_f   = (const float*)d_in[1];
    const float* W_hh_f   = (const float*)d_in[2];
    const float* b_f      = (const float*)d_in[3];
    const float* W_ih_b   = (const float*)d_in[4];
    const float* W_hh_b   = (const float*)d_in[5];
    const float* b_b      = (const float*)d_in[6];
    const float* W_lin    = (const float*)d_in[7];
    const float* b_lin    = (const float*)d_in[8];
    const float* trans    = (const float*)d_in[9];

    const int scan_smem = ROWS * 256 * (int)sizeof(float);   // 57344 B
    cudaFuncSetAttribute(lstm_scan, cudaFuncAttributeMaxDynamicSharedMemorySize, scan_smem);
    cudaFuncSetAttribute(viterbi_kernel, cudaFuncAttributeMaxDynamicSharedMemorySize,
                         SEQ * TAGS * 5);                    // 204800 B

    init_kernel<<<1, 32>>>();

    dim3 gg(GATES / 128, SEQ / 128, 2);
    gemm_xp<<<gg, 256>>>(sentence, W_ih_f, b_f, W_ih_b, b_b);

    lstm_scan<<<2 * NCTA, 256, scan_smem>>>(W_hh_f, W_hh_b);

    feats_kernel<<<SEQ, 320>>>(W_lin, b_lin);

    viterbi_kernel<<<1, 256, SEQ * TAGS * 5>>>(trans, (float*)d_out, out_size);
}